// round 16
// baseline (speedup 1.0000x reference)
#include <cuda_runtime.h>

// IF spiking neuron forward — FINAL (converged, R15 config):
//   x: [T=8, N=4194304] fp32, thresh: [1] fp32
//   mem = 0.5*thr; per t: m = mem + x[t]; s = (m>=thr); out[t] = s*thr; mem = m - s*thr
//
// Converged at the 1:1 R/W-stream roofline: 35.4us device, 6.02 TB/s
// (75.2% of 8 TB/s spec). Complete evidence table (device / DRAM%):
//   R15 .cg TPB64  batch-8:   35.39us / 76.0%   <- FINAL (ties TPB128)
//   R14 .cg TPB128 batch-8:   35.46us / 76.0%
//   R10/12/13 .cg TPB256:     35.8-36.4us / 74.2-75.5%
//   R6  plain TPB256:         36.2us / 74.7%
//   R8  plain TPB128:         36.4us / 74.4%
//   R4  .cs TPB512:           37.1us / 72.9%
//   R3  ITEMS=2 (occ 31%):    38.3us / 70.6%
//   R7  persistent 1184:      39.0us / 69.9%
//   R11 pipeline + reg cap:   41.5us / 69.5%
//   R5  .cs + reg cap:        43.1us / 69.8%
// Design laws (all A/B-proven on GB300 for this stream):
//   1. Front-batch all 8 timestep LDG.128s per thread with FREE register
//      allocation (40 regs). Any __launch_bounds__ cap makes ptxas reuse the
//      load buffer -> serialized MLP -> -6% DRAM despite +20% occupancy.
//   2. __ldcg loads: bypass L1 (single-touch data; fill is pure overhead)
//      while keeping default L2 policy. (.cs evict-first policy costs 5%.)
//   3. Small CTAs: DRAM% monotone in CTA fineness (512->64: 72.9->76.0%),
//      saturating at TPB<=128. More independent CTA streams/SM = smoother
//      load-burst interleave into L1tex/LTS at equal occupancy.
//   4. Multi-wave launch beats a persistent one-wave grid (fresh CTAs keep
//      bursts flowing; persistent CTAs phase-lock into burst-drain cycles).
// Traffic irreducible (128MiB in + 128MiB out, single touch); compute <12%.

#define T_STEPS 8
#define N_NEURONS (256 / T_STEPS * 512 * 16 * 16)   // 4,194,304
#define N4 (N_NEURONS / 4)                           // 1,048,576 float4 per timestep
#define TPB 64

__global__ __launch_bounds__(TPB) void if_forward_kernel(
    const float4* __restrict__ x,
    const float* __restrict__ thresh,
    float4* __restrict__ out)
{
    const int i = blockIdx.x * TPB + threadIdx.x;  // grid exactly covers N4
    const float thr = __ldg(thresh);

    // Front-batch all 8 timestep loads; .cg = cache at L2 only.
    float4 xv[T_STEPS];
#pragma unroll
    for (int t = 0; t < T_STEPS; t++) {
        xv[t] = __ldcg(&x[(size_t)t * N4 + i]);
    }

    float m0 = 0.5f * thr, m1 = m0, m2 = m0, m3 = m0;

#pragma unroll
    for (int t = 0; t < T_STEPS; t++) {
        m0 += xv[t].x;
        m1 += xv[t].y;
        m2 += xv[t].z;
        m3 += xv[t].w;
        float4 sp;
        sp.x = (m0 >= thr) ? thr : 0.0f;
        sp.y = (m1 >= thr) ? thr : 0.0f;
        sp.z = (m2 >= thr) ? thr : 0.0f;
        sp.w = (m3 >= thr) ? thr : 0.0f;
        m0 -= sp.x;
        m1 -= sp.y;
        m2 -= sp.z;
        m3 -= sp.w;
        out[(size_t)t * N4 + i] = sp;
    }
}

extern "C" void kernel_launch(void* const* d_in, const int* in_sizes, int n_in,
                              void* d_out, int out_size) {
    const float4* x = (const float4*)d_in[0];
    const float* thresh = (const float*)d_in[1];
    float4* out = (float4*)d_out;

    const int blocks = N4 / TPB;  // 16384, exact
    if_forward_kernel<<<blocks, TPB>>>(x, thresh, out);
}